// round 1
// baseline (speedup 1.0000x reference)
#include <cuda_runtime.h>
#include <math.h>

#define N_PIX   90000
#define HALF_PIX 45000
#define C_IN    256
#define E_CH    64
#define CROP    300
#define HEADS   2
#define DH      32

// ---------------- scratch (static device memory; no allocations) ----------------
__device__ float g_h[N_PIX * E_CH];        // [p][c] transposed; pre-BN then post-BN in place
__device__ float g_new[N_PIX * E_CH];      // [p][c] transposed attention scatter target
__device__ float g_outpre[E_CH * N_PIX];   // [c][p] pre-BN2
__device__ int   g_pix[HEADS * N_PIX];
__device__ int   g_obj[HALF_PIX];
__device__ int   g_bg[HALF_PIX];
__device__ int   g_blkcnt[360];
__device__ int   g_blkoff[360];
__device__ float g_sum1[E_CH], g_sumsq1[E_CH];
__device__ float g_scale1[E_CH], g_bias1[E_CH];
__device__ float g_scale2[E_CH], g_bias2[E_CH];

// ---------------- init: zero the atomic accumulators ----------------
__global__ void k_init() {
    int t = threadIdx.x;
    if (t < E_CH) { g_sum1[t] = 0.f; g_sumsq1[t] = 0.f; }
}

// ---------------- conv1: h_pre[p][e] = sum_c w[e][c] * x[c][p] ----------------
__global__ __launch_bounds__(256) void k_conv1(const float* __restrict__ x,
                                               const float* __restrict__ w) {
    extern __shared__ float ws[]; // 64*256 floats
    int tid = threadIdx.x;
    for (int i = tid; i < E_CH * C_IN; i += 256) ws[i] = w[i];
    __syncthreads();
    int p = blockIdx.x * 256 + tid;
    if (p >= N_PIX) return;
    float acc[E_CH];
#pragma unroll
    for (int e = 0; e < E_CH; e++) acc[e] = 0.f;
    for (int c = 0; c < C_IN; c += 4) {
        float x0 = x[(c + 0) * N_PIX + p];
        float x1 = x[(c + 1) * N_PIX + p];
        float x2 = x[(c + 2) * N_PIX + p];
        float x3 = x[(c + 3) * N_PIX + p];
#pragma unroll
        for (int e = 0; e < E_CH; e++) {
            float4 w4 = *(const float4*)&ws[e * C_IN + c];
            acc[e] += w4.x * x0 + w4.y * x1 + w4.z * x2 + w4.w * x3;
        }
    }
    float4* op = (float4*)&g_h[(size_t)p * E_CH];
#pragma unroll
    for (int e = 0; e < E_CH; e += 4)
        op[e >> 2] = make_float4(acc[e], acc[e + 1], acc[e + 2], acc[e + 3]);
}

// ---------------- BN1 stats over transposed layout (atomic partials) ----------------
__global__ void k_stats1() {
    int tid = threadIdx.x;
    int c = tid & 63;
    int sub = tid >> 6; // 0..3
    int per = (N_PIX + gridDim.x - 1) / gridDim.x;
    int p0 = blockIdx.x * per;
    int p1 = min(p0 + per, N_PIX);
    float s = 0.f, s2 = 0.f;
    for (int p = p0 + sub; p < p1; p += 4) {
        float v = g_h[(size_t)p * 64 + c];
        s += v; s2 += v * v;
    }
    __shared__ float sh[256], sh2[256];
    sh[tid] = s; sh2[tid] = s2;
    __syncthreads();
    if (sub == 0) {
        s  = sh[tid] + sh[tid + 64] + sh[tid + 128] + sh[tid + 192];
        s2 = sh2[tid] + sh2[tid + 64] + sh2[tid + 128] + sh2[tid + 192];
        atomicAdd(&g_sum1[c], s);
        atomicAdd(&g_sumsq1[c], s2);
    }
}

__global__ void k_bnfin1(const float* __restrict__ g, const float* __restrict__ b) {
    int c = threadIdx.x;
    if (c >= E_CH) return;
    float m = g_sum1[c] / (float)N_PIX;
    float var = g_sumsq1[c] / (float)N_PIX - m * m;
    float sc = g[c] * rsqrtf(var + 1e-5f);
    g_scale1[c] = sc;
    g_bias1[c]  = b[c] - m * sc;
}

__global__ void k_apply1() {
    int i = blockIdx.x * 256 + threadIdx.x;
    if (i >= N_PIX * E_CH) return;
    int c = i & 63;
    float v = g_h[i] * g_scale1[c] + g_bias1[c];
    g_h[i] = v > 0.f ? v : 0.f;
}

// ---------------- stable partition of prop (argsort of 0/1) ----------------
#define SCAN_B 352
__global__ void k_scanA(const int* __restrict__ prop) {
    int idx = blockIdx.x * 256 + threadIdx.x;
    int v = (idx < N_PIX) ? (prop[idx] != 0) : 0;
    unsigned m = __ballot_sync(0xffffffffu, v);
    __shared__ int wc[8];
    if ((threadIdx.x & 31) == 0) wc[threadIdx.x >> 5] = __popc(m);
    __syncthreads();
    if (threadIdx.x == 0) {
        int t = 0;
        for (int w = 0; w < 8; w++) t += wc[w];
        g_blkcnt[blockIdx.x] = t;
    }
}

__global__ void k_scanB() {
    __shared__ int sh[512];
    int t = threadIdx.x;
    int v0 = (t < SCAN_B) ? g_blkcnt[t] : 0;
    sh[t] = v0;
    __syncthreads();
    for (int off = 1; off < 512; off <<= 1) {
        int v = (t >= off) ? sh[t - off] : 0;
        __syncthreads();
        sh[t] += v;
        __syncthreads();
    }
    if (t < SCAN_B) g_blkoff[t] = sh[t] - v0; // exclusive
}

__global__ void k_scanC(const int* __restrict__ prop) {
    int tid = threadIdx.x;
    int idx = blockIdx.x * 256 + tid;
    int valid = idx < N_PIX;
    int v = valid ? (prop[idx] != 0) : 0;
    unsigned objm = __ballot_sync(0xffffffffu, v);
    unsigned valm = __ballot_sync(0xffffffffu, valid);
    int lane = tid & 31, w = tid >> 5;
    __shared__ int wobj[8], wval[8];
    if (lane == 0) { wobj[w] = __popc(objm); wval[w] = __popc(valm); }
    __syncthreads();
    int objbase = 0, valbase = 0;
    for (int i = 0; i < w; i++) { objbase += wobj[i]; valbase += wval[i]; }
    unsigned ltm = (1u << lane) - 1u;
    int blkobj = g_blkoff[blockIdx.x];
    if (valid) {
        if (v) {
            g_obj[blkobj + objbase + __popc(objm & ltm)] = idx;
        } else {
            int bg_before_blk = blockIdx.x * 256 - blkobj;
            int intra = (valbase - objbase) + (__popc(valm & ltm) - __popc(objm & ltm));
            g_bg[bg_before_blk + intra] = idx;
        }
    }
}

__global__ void k_pix(const int* __restrict__ rand_inds) {
    int i = blockIdx.x * 256 + threadIdx.x;
    if (i >= HEADS * N_PIX) return;
    int k = i % N_PIX;
    int r = rand_inds[i];
    g_pix[i] = (k < HALF_PIX) ? g_obj[r] : g_bg[r];
}

// ---------------- attention: one CTA per (head, seq-row) ----------------
#define ATT_THREADS 512
#define ATT_WARPS 16
#define SM_ATT_BYTES ((1024 + 2048 + 4 * 9600) * 4 + 300 * 4)

__global__ __launch_bounds__(ATT_THREADS, 1) void k_attn(const float* __restrict__ wq,
                                                         const float* __restrict__ wkv) {
    extern __shared__ float sm[];
    float* wq_s  = sm;                 // 1024
    float* wkv_s = wq_s + 1024;        // 2048
    float* seq_s = wkv_s + 2048;       // 9600 (reused as softmax p rows later)
    float* q_s   = seq_s + 9600;       // 9600
    float* k_s   = q_s + 9600;         // 9600
    float* v_s   = k_s + 9600;         // 9600
    int*   pix_s = (int*)(v_s + 9600); // 300
    float* p_rows = seq_s;             // alias (seq dead after QKV)

    int tid = threadIdx.x;
    int b = blockIdx.x;
    int head = b / CROP;
    int iblk = b - head * CROP;
    int hoff = head * DH;
    const int* pixg = g_pix + head * N_PIX + iblk * CROP;

    for (int j = tid; j < CROP; j += ATT_THREADS) pix_s[j] = pixg[j];
    for (int i = tid; i < 1024; i += ATT_THREADS) wq_s[i] = wq[i];
    for (int i = tid; i < 2048; i += ATT_THREADS) wkv_s[i] = wkv[i];
    __syncthreads();

    // gather seq[j][0..31] = h[pix[j]][hoff..hoff+31], XOR-swizzled stride-32 store
    for (int u = tid; u < CROP * 8; u += ATT_THREADS) {
        int j = u >> 3, seg = u & 7;
        float4 val = *(const float4*)&g_h[(size_t)pix_s[j] * E_CH + hoff + seg * 4];
        int pc = seg ^ (j & 7);
        *(float4*)&seq_s[j * 32 + pc * 4] = val;
    }
    __syncthreads();

    // QKV projections
    {
        int d = tid & 31;
        for (int j = tid >> 5; j < CROP; j += ATT_WARPS) {
            int sw2 = (j & 7) << 2;
            float aq = 0.f, ak = 0.f, av = 0.f;
#pragma unroll
            for (int e = 0; e < 32; e++) {
                float sv = seq_s[j * 32 + (e ^ sw2)];
                aq += sv * wq_s[e * 32 + d];
                ak += sv * wkv_s[e * 64 + d];
                av += sv * wkv_s[e * 64 + 32 + d];
            }
            int wi = j * 32 + (d ^ sw2);
            q_s[wi] = aq; k_s[wi] = ak; v_s[wi] = av;
        }
    }
    __syncthreads();

    // attention: each warp handles 2 rows at a time (shares K/V SMEM bytes)
    const float scale = 0.17677669529663687f; // 1/sqrt(32)
    int warp = tid >> 5, lane = tid & 31;
    for (int rp = warp; rp < CROP / 2; rp += ATT_WARPS) {
        int r0 = rp * 2, r1 = r0 + 1;
        float q0[32], q1[32];
        {
            int swr0 = (r0 & 7) << 2, swr1 = (r1 & 7) << 2;
#pragma unroll
            for (int dd = 0; dd < 32; dd++) {
                q0[dd] = q_s[r0 * 32 + (dd ^ swr0)];
                q1[dd] = q_s[r1 * 32 + (dd ^ swr1)];
            }
        }
        float s0[10], s1[10];
        float m0 = -1e30f, m1 = -1e30f;
#pragma unroll
        for (int jj = 0; jj < 10; jj++) {
            int j = lane + (jj << 5);
            float a0 = -1e30f, a1 = -1e30f;
            if (j < CROP) {
                const float4* kp = (const float4*)&k_s[j * 32];
                int sw = j & 7;
                a0 = 0.f; a1 = 0.f;
#pragma unroll
                for (int lc = 0; lc < 8; lc++) {
                    float4 kv = kp[lc ^ sw];
                    a0 += q0[lc*4+0]*kv.x + q0[lc*4+1]*kv.y + q0[lc*4+2]*kv.z + q0[lc*4+3]*kv.w;
                    a1 += q1[lc*4+0]*kv.x + q1[lc*4+1]*kv.y + q1[lc*4+2]*kv.z + q1[lc*4+3]*kv.w;
                }
                a0 *= scale; a1 *= scale;
            }
            s0[jj] = a0; s1[jj] = a1;
            m0 = fmaxf(m0, a0); m1 = fmaxf(m1, a1);
        }
#pragma unroll
        for (int o = 16; o > 0; o >>= 1) {
            m0 = fmaxf(m0, __shfl_xor_sync(0xffffffffu, m0, o));
            m1 = fmaxf(m1, __shfl_xor_sync(0xffffffffu, m1, o));
        }
        float e0 = 0.f, e1 = 0.f;
#pragma unroll
        for (int jj = 0; jj < 10; jj++) {
            int j = lane + (jj << 5);
            float t0 = (j < CROP) ? __expf(s0[jj] - m0) : 0.f;
            float t1 = (j < CROP) ? __expf(s1[jj] - m1) : 0.f;
            s0[jj] = t0; s1[jj] = t1;
            e0 += t0; e1 += t1;
        }
#pragma unroll
        for (int o = 16; o > 0; o >>= 1) {
            e0 += __shfl_xor_sync(0xffffffffu, e0, o);
            e1 += __shfl_xor_sync(0xffffffffu, e1, o);
        }
        float inv0 = 1.f / e0, inv1 = 1.f / e1;
        float* p0 = p_rows + (warp * 2) * CROP;
        float* p1 = p0 + CROP;
#pragma unroll
        for (int jj = 0; jj < 10; jj++) {
            int j = lane + (jj << 5);
            if (j < CROP) { p0[j] = s0[jj] * inv0; p1[j] = s1[jj] * inv1; }
        }
        __syncwarp();
        float acc0 = 0.f, acc1 = 0.f;
        for (int j4 = 0; j4 < CROP; j4 += 4) {
            float4 pw0 = *(const float4*)&p0[j4];
            float4 pw1 = *(const float4*)&p1[j4];
#pragma unroll
            for (int u = 0; u < 4; u++) {
                int j = j4 + u;
                float vv = v_s[j * 32 + (lane ^ ((j & 7) << 2))];
                float pv0 = (u == 0) ? pw0.x : (u == 1) ? pw0.y : (u == 2) ? pw0.z : pw0.w;
                float pv1 = (u == 0) ? pw1.x : (u == 1) ? pw1.y : (u == 2) ? pw1.z : pw1.w;
                acc0 += pv0 * vv;
                acc1 += pv1 * vv;
            }
        }
        // fused vals-reshape + permutation scatter:
        // o[r][c] -> t=r*32+c, d=t/300, m=t%300, new[pix[m]][hoff+d]
        {
            int t0i = r0 * 32 + lane;
            int d0 = t0i / 300, mm0 = t0i - d0 * 300;
            g_new[(size_t)pix_s[mm0] * E_CH + hoff + d0] = acc0;
            int t1i = r1 * 32 + lane;
            int d1 = t1i / 300, mm1 = t1i - d1 * 300;
            g_new[(size_t)pix_s[mm1] * E_CH + hoff + d1] = acc1;
        }
        __syncwarp();
    }
}

// ---------------- fused w_out (+relu) + conv2 (both halves) ----------------
#define SM_FUSE_BYTES ((3 * 4096 + 64) * 4)
__global__ __launch_bounds__(256) void k_fuse(const float* __restrict__ w_out,
                                              const float* __restrict__ b_out,
                                              const float* __restrict__ w2) {
    extern __shared__ float sm7[];
    float* wot  = sm7;             // [d][c] = w_out[c][d]
    float* w2a  = wot + 4096;      // [d][o] = w_conv2[o][d]
    float* w2b  = w2a + 4096;      // [c][o] = w_conv2[o][64+c]
    float* bo_s = w2b + 4096;      // 64
    int tid = threadIdx.x;
    for (int i = tid; i < 4096; i += 256) {
        int r = i >> 6, c = i & 63;
        wot[c * 64 + r] = w_out[i];
    }
    for (int i = tid; i < 4096; i += 256) {
        int o = i >> 6, d = i & 63;
        w2a[d * 64 + o] = w2[o * 128 + d];
        w2b[d * 64 + o] = w2[o * 128 + 64 + d];
    }
    if (tid < 64) bo_s[tid] = b_out[tid];
    __syncthreads();
    int p = blockIdx.x * 256 + tid;
    if (p >= N_PIX) return;

    float nv[64];
    {
        const float4* np = (const float4*)&g_new[(size_t)p * 64];
#pragma unroll
        for (int i = 0; i < 16; i++) {
            float4 v = np[i];
            nv[i*4+0] = v.x; nv[i*4+1] = v.y; nv[i*4+2] = v.z; nv[i*4+3] = v.w;
        }
    }
    float acc[64];
#pragma unroll
    for (int o = 0; o < 64; o++) acc[o] = 0.f;

    for (int dd = 0; dd < 64; dd++) {
        float xa = bo_s[dd];
#pragma unroll
        for (int c = 0; c < 64; c += 4) {
            float4 w4 = *(const float4*)&wot[dd * 64 + c];
            xa += nv[c] * w4.x + nv[c+1] * w4.y + nv[c+2] * w4.z + nv[c+3] * w4.w;
        }
        xa = fmaxf(xa, 0.f);
#pragma unroll
        for (int o = 0; o < 64; o += 4) {
            float4 w4 = *(const float4*)&w2a[dd * 64 + o];
            acc[o]   += w4.x * xa;
            acc[o+1] += w4.y * xa;
            acc[o+2] += w4.z * xa;
            acc[o+3] += w4.w * xa;
        }
    }
    for (int c4 = 0; c4 < 64; c4 += 4) {
        float4 hv = *(const float4*)&g_h[(size_t)p * 64 + c4];
        float hvv[4] = {hv.x, hv.y, hv.z, hv.w};
#pragma unroll
        for (int u = 0; u < 4; u++) {
#pragma unroll
            for (int o = 0; o < 64; o += 4) {
                float4 w4 = *(const float4*)&w2b[(c4 + u) * 64 + o];
                acc[o]   += w4.x * hvv[u];
                acc[o+1] += w4.y * hvv[u];
                acc[o+2] += w4.z * hvv[u];
                acc[o+3] += w4.w * hvv[u];
            }
        }
    }
#pragma unroll
    for (int o = 0; o < 64; o++) g_outpre[(size_t)o * N_PIX + p] = acc[o];
}

// ---------------- BN2 stats (channel-major, deterministic per-channel block) ----------------
__global__ void k_stats2(const float* __restrict__ g, const float* __restrict__ b) {
    __shared__ float sh[256], sh2[256];
    int c = blockIdx.x;
    const float* base = g_outpre + (size_t)c * N_PIX;
    float s = 0.f, s2 = 0.f;
    for (int p = threadIdx.x; p < N_PIX; p += 256) {
        float v = base[p];
        s += v; s2 += v * v;
    }
    sh[threadIdx.x] = s; sh2[threadIdx.x] = s2;
    __syncthreads();
    for (int off = 128; off > 0; off >>= 1) {
        if (threadIdx.x < off) {
            sh[threadIdx.x]  += sh[threadIdx.x + off];
            sh2[threadIdx.x] += sh2[threadIdx.x + off];
        }
        __syncthreads();
    }
    if (threadIdx.x == 0) {
        float m = sh[0] / (float)N_PIX;
        float var = sh2[0] / (float)N_PIX - m * m;
        float sc = g[c] * rsqrtf(var + 1e-5f);
        g_scale2[c] = sc;
        g_bias2[c]  = b[c] - m * sc;
    }
}

__global__ void k_apply2(float* __restrict__ out) {
    int i = blockIdx.x * 256 + threadIdx.x;
    if (i >= E_CH * N_PIX) return;
    int c = i / N_PIX;
    float v = g_outpre[i] * g_scale2[c] + g_bias2[c];
    out[i] = v > 0.f ? v : 0.f;
}

// ---------------- launch ----------------
extern "C" void kernel_launch(void* const* d_in, const int* in_sizes, int n_in,
                              void* d_out, int out_size) {
    const float* x        = (const float*)d_in[0];
    const int*   prop     = (const int*)d_in[1];
    const int*   rand_inds= (const int*)d_in[2];
    const float* w_conv1  = (const float*)d_in[3];
    const float* bn1_g    = (const float*)d_in[4];
    const float* bn1_b    = (const float*)d_in[5];
    const float* wq       = (const float*)d_in[6];
    const float* wkv      = (const float*)d_in[7];
    const float* w_out    = (const float*)d_in[8];
    const float* b_out    = (const float*)d_in[9];
    const float* w_conv2  = (const float*)d_in[10];
    const float* bn2_g    = (const float*)d_in[11];
    const float* bn2_b    = (const float*)d_in[12];
    float* out = (float*)d_out;

    size_t smem_c1 = (size_t)E_CH * C_IN * sizeof(float); // 64 KB
    cudaFuncSetAttribute(k_conv1, cudaFuncAttributeMaxDynamicSharedMemorySize, (int)smem_c1);
    cudaFuncSetAttribute(k_attn,  cudaFuncAttributeMaxDynamicSharedMemorySize, SM_ATT_BYTES);
    cudaFuncSetAttribute(k_fuse,  cudaFuncAttributeMaxDynamicSharedMemorySize, SM_FUSE_BYTES);

    k_init<<<1, 64>>>();
    k_conv1<<<(N_PIX + 255) / 256, 256, smem_c1>>>(x, w_conv1);
    k_stats1<<<88, 256>>>();
    k_bnfin1<<<1, 64>>>(bn1_g, bn1_b);
    k_apply1<<<(N_PIX * E_CH) / 256, 256>>>();
    k_scanA<<<SCAN_B, 256>>>(prop);
    k_scanB<<<1, 512>>>();
    k_scanC<<<SCAN_B, 256>>>(prop);
    k_pix<<<(HEADS * N_PIX + 255) / 256, 256>>>(rand_inds);
    k_attn<<<HEADS * CROP, ATT_THREADS, SM_ATT_BYTES>>>(wq, wkv);
    k_fuse<<<(N_PIX + 255) / 256, 256, SM_FUSE_BYTES>>>(w_out, b_out, w_conv2);
    k_stats2<<<E_CH, 256>>>(bn2_g, bn2_b);
    k_apply2<<<(E_CH * N_PIX) / 256, 256>>>(out);
}

// round 2
// speedup vs baseline: 1.0009x; 1.0009x over previous
#include <cuda_runtime.h>
#include <math.h>

#define N_PIX   90000
#define HALF_PIX 45000
#define C_IN    256
#define E_CH    64
#define CROP    300
#define HEADS   2
#define DH      32

// ---------------- scratch (static device memory; no allocations) ----------------
__device__ float g_h[N_PIX * E_CH];        // [p][c] transposed; pre-BN then post-BN in place
__device__ float g_new[N_PIX * E_CH];      // [p][c] transposed attention scatter target
__device__ float g_outpre[E_CH * N_PIX];   // [c][p] pre-BN2
__device__ int   g_pix[HEADS * N_PIX];
__device__ int   g_obj[HALF_PIX];
__device__ int   g_bg[HALF_PIX];
__device__ int   g_blkcnt[360];
__device__ int   g_blkoff[360];
__device__ float g_sum1[E_CH], g_sumsq1[E_CH];
__device__ float g_scale1[E_CH], g_bias1[E_CH];
__device__ float g_scale2[E_CH], g_bias2[E_CH];

// ---------------- init: zero the atomic accumulators ----------------
__global__ void k_init() {
    int t = threadIdx.x;
    if (t < E_CH) { g_sum1[t] = 0.f; g_sumsq1[t] = 0.f; }
}

// ---------------- conv1: h_pre[p][e] = sum_c w[e][c] * x[c][p] ----------------
__global__ __launch_bounds__(256) void k_conv1(const float* __restrict__ x,
                                               const float* __restrict__ w) {
    extern __shared__ float ws[]; // 64*256 floats
    int tid = threadIdx.x;
    for (int i = tid; i < E_CH * C_IN; i += 256) ws[i] = w[i];
    __syncthreads();
    int p = blockIdx.x * 256 + tid;
    if (p >= N_PIX) return;
    float acc[E_CH];
#pragma unroll
    for (int e = 0; e < E_CH; e++) acc[e] = 0.f;
    for (int c = 0; c < C_IN; c += 4) {
        float x0 = x[(c + 0) * N_PIX + p];
        float x1 = x[(c + 1) * N_PIX + p];
        float x2 = x[(c + 2) * N_PIX + p];
        float x3 = x[(c + 3) * N_PIX + p];
#pragma unroll
        for (int e = 0; e < E_CH; e++) {
            float4 w4 = *(const float4*)&ws[e * C_IN + c];
            acc[e] += w4.x * x0 + w4.y * x1 + w4.z * x2 + w4.w * x3;
        }
    }
    float4* op = (float4*)&g_h[(size_t)p * E_CH];
#pragma unroll
    for (int e = 0; e < E_CH; e += 4)
        op[e >> 2] = make_float4(acc[e], acc[e + 1], acc[e + 2], acc[e + 3]);
}

// ---------------- BN1 stats over transposed layout (atomic partials) ----------------
__global__ void k_stats1() {
    int tid = threadIdx.x;
    int c = tid & 63;
    int sub = tid >> 6; // 0..3
    int per = (N_PIX + gridDim.x - 1) / gridDim.x;
    int p0 = blockIdx.x * per;
    int p1 = min(p0 + per, N_PIX);
    float s = 0.f, s2 = 0.f;
    for (int p = p0 + sub; p < p1; p += 4) {
        float v = g_h[(size_t)p * 64 + c];
        s += v; s2 += v * v;
    }
    __shared__ float sh[256], sh2[256];
    sh[tid] = s; sh2[tid] = s2;
    __syncthreads();
    if (sub == 0) {
        s  = sh[tid] + sh[tid + 64] + sh[tid + 128] + sh[tid + 192];
        s2 = sh2[tid] + sh2[tid + 64] + sh2[tid + 128] + sh2[tid + 192];
        atomicAdd(&g_sum1[c], s);
        atomicAdd(&g_sumsq1[c], s2);
    }
}

__global__ void k_bnfin1(const float* __restrict__ g, const float* __restrict__ b) {
    int c = threadIdx.x;
    if (c >= E_CH) return;
    float m = g_sum1[c] / (float)N_PIX;
    float var = g_sumsq1[c] / (float)N_PIX - m * m;
    float sc = g[c] * rsqrtf(var + 1e-5f);
    g_scale1[c] = sc;
    g_bias1[c]  = b[c] - m * sc;
}

__global__ void k_apply1() {
    int i = blockIdx.x * 256 + threadIdx.x;
    if (i >= N_PIX * E_CH) return;
    int c = i & 63;
    float v = g_h[i] * g_scale1[c] + g_bias1[c];
    g_h[i] = v > 0.f ? v : 0.f;
}

// ---------------- stable partition of prop (argsort of 0/1) ----------------
#define SCAN_B 352
__global__ void k_scanA(const int* __restrict__ prop) {
    int idx = blockIdx.x * 256 + threadIdx.x;
    int v = (idx < N_PIX) ? (prop[idx] != 0) : 0;
    unsigned m = __ballot_sync(0xffffffffu, v);
    __shared__ int wc[8];
    if ((threadIdx.x & 31) == 0) wc[threadIdx.x >> 5] = __popc(m);
    __syncthreads();
    if (threadIdx.x == 0) {
        int t = 0;
        for (int w = 0; w < 8; w++) t += wc[w];
        g_blkcnt[blockIdx.x] = t;
    }
}

__global__ void k_scanB() {
    __shared__ int sh[512];
    int t = threadIdx.x;
    int v0 = (t < SCAN_B) ? g_blkcnt[t] : 0;
    sh[t] = v0;
    __syncthreads();
    for (int off = 1; off < 512; off <<= 1) {
        int v = (t >= off) ? sh[t - off] : 0;
        __syncthreads();
        sh[t] += v;
        __syncthreads();
    }
    if (t < SCAN_B) g_blkoff[t] = sh[t] - v0; // exclusive
}

__global__ void k_scanC(const int* __restrict__ prop) {
    int tid = threadIdx.x;
    int idx = blockIdx.x * 256 + tid;
    int valid = idx < N_PIX;
    int v = valid ? (prop[idx] != 0) : 0;
    unsigned objm = __ballot_sync(0xffffffffu, v);
    unsigned valm = __ballot_sync(0xffffffffu, valid);
    int lane = tid & 31, w = tid >> 5;
    __shared__ int wobj[8], wval[8];
    if (lane == 0) { wobj[w] = __popc(objm); wval[w] = __popc(valm); }
    __syncthreads();
    int objbase = 0, valbase = 0;
    for (int i = 0; i < w; i++) { objbase += wobj[i]; valbase += wval[i]; }
    unsigned ltm = (1u << lane) - 1u;
    int blkobj = g_blkoff[blockIdx.x];
    if (valid) {
        if (v) {
            g_obj[blkobj + objbase + __popc(objm & ltm)] = idx;
        } else {
            int bg_before_blk = blockIdx.x * 256 - blkobj;
            int intra = (valbase - objbase) + (__popc(valm & ltm) - __popc(objm & ltm));
            g_bg[bg_before_blk + intra] = idx;
        }
    }
}

__global__ void k_pix(const int* __restrict__ rand_inds) {
    int i = blockIdx.x * 256 + threadIdx.x;
    if (i >= HEADS * N_PIX) return;
    int k = i % N_PIX;
    int r = rand_inds[i];
    g_pix[i] = (k < HALF_PIX) ? g_obj[r] : g_bg[r];
}

// ---------------- attention: one CTA per (head, seq-row) ----------------
#define ATT_THREADS 512
#define ATT_WARPS 16
#define SM_ATT_BYTES ((1024 + 2048 + 4 * 9600) * 4 + 300 * 4)

__global__ __launch_bounds__(ATT_THREADS, 1) void k_attn(const float* __restrict__ wq,
                                                         const float* __restrict__ wkv) {
    extern __shared__ float sm[];
    float* wq_s  = sm;                 // 1024
    float* wkv_s = wq_s + 1024;        // 2048
    float* seq_s = wkv_s + 2048;       // 9600 (reused as softmax p rows later)
    float* q_s   = seq_s + 9600;       // 9600
    float* k_s   = q_s + 9600;         // 9600
    float* v_s   = k_s + 9600;         // 9600
    int*   pix_s = (int*)(v_s + 9600); // 300
    float* p_rows = seq_s;             // alias (seq dead after QKV)

    int tid = threadIdx.x;
    int b = blockIdx.x;
    int head = b / CROP;
    int iblk = b - head * CROP;
    int hoff = head * DH;
    const int* pixg = g_pix + head * N_PIX + iblk * CROP;

    for (int j = tid; j < CROP; j += ATT_THREADS) pix_s[j] = pixg[j];
    for (int i = tid; i < 1024; i += ATT_THREADS) wq_s[i] = wq[i];
    for (int i = tid; i < 2048; i += ATT_THREADS) wkv_s[i] = wkv[i];
    __syncthreads();

    // gather seq[j][0..31] = h[pix[j]][hoff..hoff+31], XOR-swizzled stride-32 store
    for (int u = tid; u < CROP * 8; u += ATT_THREADS) {
        int j = u >> 3, seg = u & 7;
        float4 val = *(const float4*)&g_h[(size_t)pix_s[j] * E_CH + hoff + seg * 4];
        int pc = seg ^ (j & 7);
        *(float4*)&seq_s[j * 32 + pc * 4] = val;
    }
    __syncthreads();

    // QKV projections
    {
        int d = tid & 31;
        for (int j = tid >> 5; j < CROP; j += ATT_WARPS) {
            int sw2 = (j & 7) << 2;
            float aq = 0.f, ak = 0.f, av = 0.f;
#pragma unroll
            for (int e = 0; e < 32; e++) {
                float sv = seq_s[j * 32 + (e ^ sw2)];
                aq += sv * wq_s[e * 32 + d];
                ak += sv * wkv_s[e * 64 + d];
                av += sv * wkv_s[e * 64 + 32 + d];
            }
            int wi = j * 32 + (d ^ sw2);
            q_s[wi] = aq; k_s[wi] = ak; v_s[wi] = av;
        }
    }
    __syncthreads();

    // attention: each warp handles 2 rows at a time (shares K/V SMEM bytes)
    const float scale = 0.17677669529663687f; // 1/sqrt(32)
    int warp = tid >> 5, lane = tid & 31;
    for (int rp = warp; rp < CROP / 2; rp += ATT_WARPS) {
        int r0 = rp * 2, r1 = r0 + 1;
        float q0[32], q1[32];
        {
            int swr0 = (r0 & 7) << 2, swr1 = (r1 & 7) << 2;
#pragma unroll
            for (int dd = 0; dd < 32; dd++) {
                q0[dd] = q_s[r0 * 32 + (dd ^ swr0)];
                q1[dd] = q_s[r1 * 32 + (dd ^ swr1)];
            }
        }
        float s0[10], s1[10];
        float m0 = -1e30f, m1 = -1e30f;
#pragma unroll
        for (int jj = 0; jj < 10; jj++) {
            int j = lane + (jj << 5);
            float a0 = -1e30f, a1 = -1e30f;
            if (j < CROP) {
                const float4* kp = (const float4*)&k_s[j * 32];
                int sw = j & 7;
                a0 = 0.f; a1 = 0.f;
#pragma unroll
                for (int lc = 0; lc < 8; lc++) {
                    float4 kv = kp[lc ^ sw];
                    a0 += q0[lc*4+0]*kv.x + q0[lc*4+1]*kv.y + q0[lc*4+2]*kv.z + q0[lc*4+3]*kv.w;
                    a1 += q1[lc*4+0]*kv.x + q1[lc*4+1]*kv.y + q1[lc*4+2]*kv.z + q1[lc*4+3]*kv.w;
                }
                a0 *= scale; a1 *= scale;
            }
            s0[jj] = a0; s1[jj] = a1;
            m0 = fmaxf(m0, a0); m1 = fmaxf(m1, a1);
        }
#pragma unroll
        for (int o = 16; o > 0; o >>= 1) {
            m0 = fmaxf(m0, __shfl_xor_sync(0xffffffffu, m0, o));
            m1 = fmaxf(m1, __shfl_xor_sync(0xffffffffu, m1, o));
        }
        float e0 = 0.f, e1 = 0.f;
#pragma unroll
        for (int jj = 0; jj < 10; jj++) {
            int j = lane + (jj << 5);
            float t0 = (j < CROP) ? __expf(s0[jj] - m0) : 0.f;
            float t1 = (j < CROP) ? __expf(s1[jj] - m1) : 0.f;
            s0[jj] = t0; s1[jj] = t1;
            e0 += t0; e1 += t1;
        }
#pragma unroll
        for (int o = 16; o > 0; o >>= 1) {
            e0 += __shfl_xor_sync(0xffffffffu, e0, o);
            e1 += __shfl_xor_sync(0xffffffffu, e1, o);
        }
        float inv0 = 1.f / e0, inv1 = 1.f / e1;
        float* p0 = p_rows + (warp * 2) * CROP;
        float* p1 = p0 + CROP;
#pragma unroll
        for (int jj = 0; jj < 10; jj++) {
            int j = lane + (jj << 5);
            if (j < CROP) { p0[j] = s0[jj] * inv0; p1[j] = s1[jj] * inv1; }
        }
        __syncwarp();
        float acc0 = 0.f, acc1 = 0.f;
        for (int j4 = 0; j4 < CROP; j4 += 4) {
            float4 pw0 = *(const float4*)&p0[j4];
            float4 pw1 = *(const float4*)&p1[j4];
#pragma unroll
            for (int u = 0; u < 4; u++) {
                int j = j4 + u;
                float vv = v_s[j * 32 + (lane ^ ((j & 7) << 2))];
                float pv0 = (u == 0) ? pw0.x : (u == 1) ? pw0.y : (u == 2) ? pw0.z : pw0.w;
                float pv1 = (u == 0) ? pw1.x : (u == 1) ? pw1.y : (u == 2) ? pw1.z : pw1.w;
                acc0 += pv0 * vv;
                acc1 += pv1 * vv;
            }
        }
        // fused vals-reshape + permutation scatter:
        // o[r][c] -> t=r*32+c, d=t/300, m=t%300, new[pix[m]][hoff+d]
        {
            int t0i = r0 * 32 + lane;
            int d0 = t0i / 300, mm0 = t0i - d0 * 300;
            g_new[(size_t)pix_s[mm0] * E_CH + hoff + d0] = acc0;
            int t1i = r1 * 32 + lane;
            int d1 = t1i / 300, mm1 = t1i - d1 * 300;
            g_new[(size_t)pix_s[mm1] * E_CH + hoff + d1] = acc1;
        }
        __syncwarp();
    }
}

// ---------------- fused w_out (+relu) + conv2 (both halves) ----------------
#define SM_FUSE_BYTES ((3 * 4096 + 64) * 4)
__global__ __launch_bounds__(256) void k_fuse(const float* __restrict__ w_out,
                                              const float* __restrict__ b_out,
                                              const float* __restrict__ w2) {
    extern __shared__ float sm7[];
    float* wot  = sm7;             // [d][c] = w_out[c][d]
    float* w2a  = wot + 4096;      // [d][o] = w_conv2[o][d]
    float* w2b  = w2a + 4096;      // [c][o] = w_conv2[o][64+c]
    float* bo_s = w2b + 4096;      // 64
    int tid = threadIdx.x;
    for (int i = tid; i < 4096; i += 256) {
        int r = i >> 6, c = i & 63;
        wot[c * 64 + r] = w_out[i];
    }
    for (int i = tid; i < 4096; i += 256) {
        int o = i >> 6, d = i & 63;
        w2a[d * 64 + o] = w2[o * 128 + d];
        w2b[d * 64 + o] = w2[o * 128 + 64 + d];
    }
    if (tid < 64) bo_s[tid] = b_out[tid];
    __syncthreads();
    int p = blockIdx.x * 256 + tid;
    if (p >= N_PIX) return;

    float nv[64];
    {
        const float4* np = (const float4*)&g_new[(size_t)p * 64];
#pragma unroll
        for (int i = 0; i < 16; i++) {
            float4 v = np[i];
            nv[i*4+0] = v.x; nv[i*4+1] = v.y; nv[i*4+2] = v.z; nv[i*4+3] = v.w;
        }
    }
    float acc[64];
#pragma unroll
    for (int o = 0; o < 64; o++) acc[o] = 0.f;

    for (int dd = 0; dd < 64; dd++) {
        float xa = bo_s[dd];
#pragma unroll
        for (int c = 0; c < 64; c += 4) {
            float4 w4 = *(const float4*)&wot[dd * 64 + c];
            xa += nv[c] * w4.x + nv[c+1] * w4.y + nv[c+2] * w4.z + nv[c+3] * w4.w;
        }
        xa = fmaxf(xa, 0.f);
#pragma unroll
        for (int o = 0; o < 64; o += 4) {
            float4 w4 = *(const float4*)&w2a[dd * 64 + o];
            acc[o]   += w4.x * xa;
            acc[o+1] += w4.y * xa;
            acc[o+2] += w4.z * xa;
            acc[o+3] += w4.w * xa;
        }
    }
    for (int c4 = 0; c4 < 64; c4 += 4) {
        float4 hv = *(const float4*)&g_h[(size_t)p * 64 + c4];
        float hvv[4] = {hv.x, hv.y, hv.z, hv.w};
#pragma unroll
        for (int u = 0; u < 4; u++) {
#pragma unroll
            for (int o = 0; o < 64; o += 4) {
                float4 w4 = *(const float4*)&w2b[(c4 + u) * 64 + o];
                acc[o]   += w4.x * hvv[u];
                acc[o+1] += w4.y * hvv[u];
                acc[o+2] += w4.z * hvv[u];
                acc[o+3] += w4.w * hvv[u];
            }
        }
    }
#pragma unroll
    for (int o = 0; o < 64; o++) g_outpre[(size_t)o * N_PIX + p] = acc[o];
}

// ---------------- BN2 stats (channel-major, deterministic per-channel block) ----------------
__global__ void k_stats2(const float* __restrict__ g, const float* __restrict__ b) {
    __shared__ float sh[256], sh2[256];
    int c = blockIdx.x;
    const float* base = g_outpre + (size_t)c * N_PIX;
    float s = 0.f, s2 = 0.f;
    for (int p = threadIdx.x; p < N_PIX; p += 256) {
        float v = base[p];
        s += v; s2 += v * v;
    }
    sh[threadIdx.x] = s; sh2[threadIdx.x] = s2;
    __syncthreads();
    for (int off = 128; off > 0; off >>= 1) {
        if (threadIdx.x < off) {
            sh[threadIdx.x]  += sh[threadIdx.x + off];
            sh2[threadIdx.x] += sh2[threadIdx.x + off];
        }
        __syncthreads();
    }
    if (threadIdx.x == 0) {
        float m = sh[0] / (float)N_PIX;
        float var = sh2[0] / (float)N_PIX - m * m;
        float sc = g[c] * rsqrtf(var + 1e-5f);
        g_scale2[c] = sc;
        g_bias2[c]  = b[c] - m * sc;
    }
}

__global__ void k_apply2(float* __restrict__ out) {
    int i = blockIdx.x * 256 + threadIdx.x;
    if (i >= E_CH * N_PIX) return;
    int c = i / N_PIX;
    float v = g_outpre[i] * g_scale2[c] + g_bias2[c];
    out[i] = v > 0.f ? v : 0.f;
}

// ---------------- launch ----------------
extern "C" void kernel_launch(void* const* d_in, const int* in_sizes, int n_in,
                              void* d_out, int out_size) {
    const float* x        = (const float*)d_in[0];
    const int*   prop     = (const int*)d_in[1];
    const int*   rand_inds= (const int*)d_in[2];
    const float* w_conv1  = (const float*)d_in[3];
    const float* bn1_g    = (const float*)d_in[4];
    const float* bn1_b    = (const float*)d_in[5];
    const float* wq       = (const float*)d_in[6];
    const float* wkv      = (const float*)d_in[7];
    const float* w_out    = (const float*)d_in[8];
    const float* b_out    = (const float*)d_in[9];
    const float* w_conv2  = (const float*)d_in[10];
    const float* bn2_g    = (const float*)d_in[11];
    const float* bn2_b    = (const float*)d_in[12];
    float* out = (float*)d_out;

    size_t smem_c1 = (size_t)E_CH * C_IN * sizeof(float); // 64 KB
    cudaFuncSetAttribute(k_conv1, cudaFuncAttributeMaxDynamicSharedMemorySize, (int)smem_c1);
    cudaFuncSetAttribute(k_attn,  cudaFuncAttributeMaxDynamicSharedMemorySize, SM_ATT_BYTES);
    cudaFuncSetAttribute(k_fuse,  cudaFuncAttributeMaxDynamicSharedMemorySize, SM_FUSE_BYTES);

    k_init<<<1, 64>>>();
    k_conv1<<<(N_PIX + 255) / 256, 256, smem_c1>>>(x, w_conv1);
    k_stats1<<<88, 256>>>();
    k_bnfin1<<<1, 64>>>(bn1_g, bn1_b);
    k_apply1<<<(N_PIX * E_CH) / 256, 256>>>();
    k_scanA<<<SCAN_B, 256>>>(prop);
    k_scanB<<<1, 512>>>();
    k_scanC<<<SCAN_B, 256>>>(prop);
    k_pix<<<(HEADS * N_PIX + 255) / 256, 256>>>(rand_inds);
    k_attn<<<HEADS * CROP, ATT_THREADS, SM_ATT_BYTES>>>(wq, wkv);
    k_fuse<<<(N_PIX + 255) / 256, 256, SM_FUSE_BYTES>>>(w_out, b_out, w_conv2);
    k_stats2<<<E_CH, 256>>>(bn2_g, bn2_b);
    k_apply2<<<(E_CH * N_PIX) / 256, 256>>>(out);
}

// round 3
// speedup vs baseline: 1.0791x; 1.0781x over previous
#include <cuda_runtime.h>
#include <math.h>

#define N_PIX    90000
#define HALF_PIX 45000
#define C_IN     256
#define E_CH     64
#define CROP     300
#define HEADS    2
#define DH       32

typedef unsigned long long ull;

__device__ __forceinline__ void fma2(ull& d, ull a, ull b) {
    asm("fma.rn.f32x2 %0, %1, %2, %0;" : "+l"(d) : "l"(a), "l"(b));
}
__device__ __forceinline__ ull add2(ull a, ull b) {
    ull r; asm("add.rn.f32x2 %0, %1, %2;" : "=l"(r) : "l"(a), "l"(b)); return r;
}
__device__ __forceinline__ ull mul2(ull a, ull b) {
    ull r; asm("mul.rn.f32x2 %0, %1, %2;" : "=l"(r) : "l"(a), "l"(b)); return r;
}
__device__ __forceinline__ ull fdup(float v) {
    ull r; asm("mov.b64 %0, {%1, %1};" : "=l"(r) : "f"(v)); return r;
}
__device__ __forceinline__ float2 u2f(ull v) {
    float2 f; asm("mov.b64 {%0, %1}, %2;" : "=f"(f.x), "=f"(f.y) : "l"(v)); return f;
}
__device__ __forceinline__ float hsum2(ull v) { float2 f = u2f(v); return f.x + f.y; }

// ---------------- scratch ----------------
__device__ float g_h[N_PIX * E_CH];        // [p][c] pre-BN1
__device__ float g_new[N_PIX * E_CH];      // [p][c] attention scatter target
__device__ float g_outpre[E_CH * N_PIX];   // [c][p] pre-BN2
__device__ int   g_obj[HALF_PIX];
__device__ int   g_bg[HALF_PIX];
__device__ int   g_blkcnt[360];
__device__ int   g_blkoff[360];
__device__ float g_sum1[E_CH], g_sumsq1[E_CH];
__device__ float g_scale2[E_CH], g_bias2[E_CH];

__global__ void k_init() {
    int t = threadIdx.x;
    if (t < E_CH)  g_sum1[t] = 0.f;
    else if (t < 2 * E_CH) g_sumsq1[t - E_CH] = 0.f;
}

// ---------------- stable partition of prop ----------------
#define SCAN_B 352
__global__ void k_scanA(const int* __restrict__ prop) {
    int idx = blockIdx.x * 256 + threadIdx.x;
    int v = (idx < N_PIX) ? (prop[idx] != 0) : 0;
    unsigned m = __ballot_sync(0xffffffffu, v);
    __shared__ int wc[8];
    if ((threadIdx.x & 31) == 0) wc[threadIdx.x >> 5] = __popc(m);
    __syncthreads();
    if (threadIdx.x == 0) {
        int t = 0;
        for (int w = 0; w < 8; w++) t += wc[w];
        g_blkcnt[blockIdx.x] = t;
    }
}

__global__ void k_scanB() {
    __shared__ int sh[512];
    int t = threadIdx.x;
    int v0 = (t < SCAN_B) ? g_blkcnt[t] : 0;
    sh[t] = v0;
    __syncthreads();
    for (int off = 1; off < 512; off <<= 1) {
        int v = (t >= off) ? sh[t - off] : 0;
        __syncthreads();
        sh[t] += v;
        __syncthreads();
    }
    if (t < SCAN_B) g_blkoff[t] = sh[t] - v0;
}

__global__ void k_scanC(const int* __restrict__ prop) {
    int tid = threadIdx.x;
    int idx = blockIdx.x * 256 + tid;
    int valid = idx < N_PIX;
    int v = valid ? (prop[idx] != 0) : 0;
    unsigned objm = __ballot_sync(0xffffffffu, v);
    unsigned valm = __ballot_sync(0xffffffffu, valid);
    int lane = tid & 31, w = tid >> 5;
    __shared__ int wobj[8], wval[8];
    if (lane == 0) { wobj[w] = __popc(objm); wval[w] = __popc(valm); }
    __syncthreads();
    int objbase = 0, valbase = 0;
    for (int i = 0; i < w; i++) { objbase += wobj[i]; valbase += wval[i]; }
    unsigned ltm = (1u << lane) - 1u;
    int blkobj = g_blkoff[blockIdx.x];
    if (valid) {
        if (v) {
            g_obj[blkobj + objbase + __popc(objm & ltm)] = idx;
        } else {
            int bg_before_blk = blockIdx.x * 256 - blkobj;
            int intra = (valbase - objbase) + (__popc(valm & ltm) - __popc(objm & ltm));
            g_bg[bg_before_blk + intra] = idx;
        }
    }
}

// ---------------- conv1 with fused BN1 stats ----------------
// h_pre[p][e] = sum_c w[e][c]*x[c][p]; f32x2 packed along e.
__global__ __launch_bounds__(256) void k_conv1(const float* __restrict__ x,
                                               const float* __restrict__ w) {
    extern __shared__ float ws[]; // transposed [c][e]: ws[c*64+e] = w[e*256+c]
    int tid = threadIdx.x;
    for (int i = tid; i < E_CH * C_IN; i += 256) {
        int e = i >> 8, c = i & 255;
        ws[c * 64 + e] = w[i];
    }
    __syncthreads();
    int p = blockIdx.x * 256 + tid;
    bool valid = p < N_PIX;

    ull acc2[32];
#pragma unroll
    for (int i = 0; i < 32; i++) acc2[i] = 0ull;

    if (valid) {
#pragma unroll 2
        for (int c = 0; c < C_IN; c++) {
            ull xd = fdup(__ldg(&x[(size_t)c * N_PIX + p]));
            const float* wr = &ws[c * 64];
#pragma unroll
            for (int i = 0; i < 16; i++) {
                ulonglong2 wv = *(const ulonglong2*)&wr[i * 4];
                fma2(acc2[2 * i],     wv.x, xd);
                fma2(acc2[2 * i + 1], wv.y, xd);
            }
        }
        // store h_pre
        ull* op = (ull*)&g_h[(size_t)p * 64];
#pragma unroll
        for (int i = 0; i < 32; i++) op[i] = acc2[i];
    }

    // fused BN1 stats: warp shuffle reduce then global atomics (lane 0)
    int lane = tid & 31;
#pragma unroll 4
    for (int k = 0; k < 32; k++) {
        ull s = acc2[k];
        ull q = mul2(acc2[k], acc2[k]);
#pragma unroll
        for (int o = 16; o > 0; o >>= 1) {
            s = add2(s, __shfl_xor_sync(0xffffffffu, s, o));
            q = add2(q, __shfl_xor_sync(0xffffffffu, q, o));
        }
        if (lane == 0) {
            float2 sf = u2f(s), qf = u2f(q);
            atomicAdd(&g_sum1[2 * k],     sf.x);
            atomicAdd(&g_sum1[2 * k + 1], sf.y);
            atomicAdd(&g_sumsq1[2 * k],     qf.x);
            atomicAdd(&g_sumsq1[2 * k + 1], qf.y);
        }
    }
}

// ---------------- attention ----------------
#define ATT_THREADS 256
#define SM_ATT_BYTES ((128 + 1024 + 2048 + 4 * 9600 + 300) * 4)

__global__ __launch_bounds__(ATT_THREADS, 1) void k_attn(const float* __restrict__ wq,
                                                         const float* __restrict__ wkv,
                                                         const int* __restrict__ rand_inds,
                                                         const float* __restrict__ bn1_g,
                                                         const float* __restrict__ bn1_b) {
    extern __shared__ float sm[];
    float* sc1   = sm;                  // 64
    float* bi1   = sm + 64;             // 64
    float* wq_s  = sm + 128;            // 1024
    float* wkv_s = wq_s + 1024;         // 2048
    float* seq_s = wkv_s + 2048;        // 9600 (aliased as p_rows after QKV)
    float* q_s   = seq_s + 9600;        // 9600
    float* k_s   = q_s + 9600;          // 9600
    float* v_t   = k_s + 9600;          // 9600: [d][300]
    int*   pix_s = (int*)(v_t + 9600);  // 300
    float* p_rows = seq_s;

    int tid = threadIdx.x, warp = tid >> 5, lane = tid & 31;
    int b = blockIdx.x;
    int head = b / CROP;
    int iblk = b - head * CROP;
    int hoff = head * DH;

    if (tid < 64) {
        float m = g_sum1[tid] * (1.f / (float)N_PIX);
        float var = g_sumsq1[tid] * (1.f / (float)N_PIX) - m * m;
        float sc = bn1_g[tid] * rsqrtf(var + 1e-5f);
        sc1[tid] = sc;
        bi1[tid] = bn1_b[tid] - m * sc;
    }
    const int* src = (iblk < CROP / 2) ? g_obj : g_bg;
    const int* ri = rand_inds + (size_t)head * N_PIX + (size_t)iblk * CROP;
    for (int j = tid; j < CROP; j += ATT_THREADS) pix_s[j] = src[ri[j]];
    for (int i = tid; i < 1024; i += ATT_THREADS) wq_s[i] = wq[i];
    for (int i = tid; i < 2048; i += ATT_THREADS) wkv_s[i] = wkv[i];
    __syncthreads();

    // gather seq[j][d] = relu(bn1(h_pre[pix[j]][hoff+d])), XOR-swizzled stride-32
    for (int u = tid; u < CROP * 8; u += ATT_THREADS) {
        int j = u >> 3, seg = u & 7;
        int ch = hoff + seg * 4;
        float4 v = *(const float4*)&g_h[(size_t)pix_s[j] * 64 + ch];
        float4 s4 = *(const float4*)&sc1[ch];
        float4 b4 = *(const float4*)&bi1[ch];
        v.x = fmaxf(fmaf(v.x, s4.x, b4.x), 0.f);
        v.y = fmaxf(fmaf(v.y, s4.y, b4.y), 0.f);
        v.z = fmaxf(fmaf(v.z, s4.z, b4.z), 0.f);
        v.w = fmaxf(fmaf(v.w, s4.w, b4.w), 0.f);
        int pc = seg ^ (j & 7);
        *(float4*)&seq_s[j * 32 + pc * 4] = v;
    }
    __syncthreads();

    // QKV: q/k swizzled [j][32]; v transposed [d][300]
    {
        int d = lane;
        for (int j = warp; j < CROP; j += 8) {
            int sw2 = (j & 7) << 2;
            float aq = 0.f, ak = 0.f, av = 0.f;
#pragma unroll
            for (int e = 0; e < 32; e++) {
                float sv = seq_s[j * 32 + (e ^ sw2)];
                aq += sv * wq_s[e * 32 + d];
                ak += sv * wkv_s[e * 64 + d];
                av += sv * wkv_s[e * 64 + 32 + d];
            }
            int wi = j * 32 + (d ^ sw2);
            q_s[wi] = aq;
            k_s[wi] = ak;
            v_t[d * 300 + j] = av;
        }
    }
    __syncthreads();

    const float scale = 0.17677669529663687f; // 1/sqrt(32)
    for (int rp = warp; rp < 75; rp += 8) {
        int r0 = rp * 4;
        // q registers for 4 rows, packed (d,d+1) pairs
        ull q2[4][16];
#pragma unroll
        for (int r = 0; r < 4; r++) {
            int row = r0 + r, sw = row & 7;
#pragma unroll
            for (int c = 0; c < 8; c++) {
                ulonglong2 t = *(const ulonglong2*)&q_s[row * 32 + ((c ^ sw) << 2)];
                q2[r][2 * c] = t.x;
                q2[r][2 * c + 1] = t.y;
            }
        }
        float mx0 = -1e30f, mx1 = -1e30f, mx2 = -1e30f, mx3 = -1e30f;
        // scores -> p_rows (raw logits), max tracked in regs
#pragma unroll
        for (int jj = 0; jj < 10; jj++) {
            int j = lane + (jj << 5);
            if (j < CROP) {
                ull a0 = 0, a1 = 0, a2 = 0, a3 = 0;
                int sw = j & 7;
#pragma unroll
                for (int c = 0; c < 8; c++) {
                    ulonglong2 kv = *(const ulonglong2*)&k_s[j * 32 + ((c ^ sw) << 2)];
                    fma2(a0, q2[0][2 * c], kv.x); fma2(a0, q2[0][2 * c + 1], kv.y);
                    fma2(a1, q2[1][2 * c], kv.x); fma2(a1, q2[1][2 * c + 1], kv.y);
                    fma2(a2, q2[2][2 * c], kv.x); fma2(a2, q2[2][2 * c + 1], kv.y);
                    fma2(a3, q2[3][2 * c], kv.x); fma2(a3, q2[3][2 * c + 1], kv.y);
                }
                float s0 = hsum2(a0) * scale;
                float s1 = hsum2(a1) * scale;
                float s2 = hsum2(a2) * scale;
                float s3 = hsum2(a3) * scale;
                p_rows[(warp * 4 + 0) * 300 + j] = s0;
                p_rows[(warp * 4 + 1) * 300 + j] = s1;
                p_rows[(warp * 4 + 2) * 300 + j] = s2;
                p_rows[(warp * 4 + 3) * 300 + j] = s3;
                mx0 = fmaxf(mx0, s0); mx1 = fmaxf(mx1, s1);
                mx2 = fmaxf(mx2, s2); mx3 = fmaxf(mx3, s3);
            }
        }
#pragma unroll
        for (int o = 16; o > 0; o >>= 1) {
            mx0 = fmaxf(mx0, __shfl_xor_sync(0xffffffffu, mx0, o));
            mx1 = fmaxf(mx1, __shfl_xor_sync(0xffffffffu, mx1, o));
            mx2 = fmaxf(mx2, __shfl_xor_sync(0xffffffffu, mx2, o));
            mx3 = fmaxf(mx3, __shfl_xor_sync(0xffffffffu, mx3, o));
        }
        __syncwarp();
        float mxa[4] = {mx0, mx1, mx2, mx3};
        // softmax per row in-place
#pragma unroll
        for (int r = 0; r < 4; r++) {
            float* pr = &p_rows[(warp * 4 + r) * 300];
            float ev[10];
            float sum = 0.f;
#pragma unroll
            for (int jj = 0; jj < 10; jj++) {
                int j = lane + (jj << 5);
                float e = (j < CROP) ? __expf(pr[j] - mxa[r]) : 0.f;
                ev[jj] = e;
                sum += e;
            }
#pragma unroll
            for (int o = 16; o > 0; o >>= 1) sum += __shfl_xor_sync(0xffffffffu, sum, o);
            float inv = 1.f / sum;
#pragma unroll
            for (int jj = 0; jj < 10; jj++) {
                int j = lane + (jj << 5);
                if (j < CROP) pr[j] = ev[jj] * inv;
            }
        }
        __syncwarp();
        // PV: lane = d, packed along j pairs
        ull o2[4] = {0, 0, 0, 0};
        const float* vrow = &v_t[lane * 300];
#pragma unroll 5
        for (int j4 = 0; j4 < 75; j4++) {
            ulonglong2 vv = *(const ulonglong2*)&vrow[j4 * 4];
#pragma unroll
            for (int r = 0; r < 4; r++) {
                ulonglong2 pv = *(const ulonglong2*)&p_rows[(warp * 4 + r) * 300 + j4 * 4];
                fma2(o2[r], pv.x, vv.x);
                fma2(o2[r], pv.y, vv.y);
            }
        }
        // fused vals-reshape + permutation scatter
#pragma unroll
        for (int r = 0; r < 4; r++) {
            float ov = hsum2(o2[r]);
            int t = (r0 + r) * 32 + lane;
            int d = t / 300, mm = t - d * 300;
            g_new[(size_t)pix_s[mm] * 64 + hoff + d] = ov;
        }
        __syncwarp();
    }
}

// ---------------- fused w_out(+relu) + conv2, BN1 applied to h inline ----------------
#define SM_FUSE_BYTES ((3 * 4096 + 64 + 128) * 4)
__global__ __launch_bounds__(256) void k_fuse(const float* __restrict__ w_out,
                                              const float* __restrict__ b_out,
                                              const float* __restrict__ w2,
                                              const float* __restrict__ bn1_g,
                                              const float* __restrict__ bn1_b) {
    extern __shared__ float sf[];
    float* wot  = sf;              // [d][c] = w_out[c][d]
    float* w2a  = wot + 4096;      // [d][o] = w_conv2[o][d]
    float* w2b  = w2a + 4096;      // [c][o] = w_conv2[o][64+c]
    float* bo_s = w2b + 4096;      // 64
    float* sc1  = bo_s + 64;       // 64
    float* bi1  = sc1 + 64;        // 64
    int tid = threadIdx.x;
    for (int i = tid; i < 4096; i += 256) {
        int r = i >> 6, c = i & 63;
        wot[c * 64 + r] = w_out[i];
        w2a[c * 64 + r] = w2[r * 128 + c];          // w2a[d][o]=w2[o*128+d] (r=o,c=d)
        w2b[c * 64 + r] = w2[r * 128 + 64 + c];     // w2b[c'][o]
    }
    if (tid < 64) {
        bo_s[tid] = b_out[tid];
        float m = g_sum1[tid] * (1.f / (float)N_PIX);
        float var = g_sumsq1[tid] * (1.f / (float)N_PIX) - m * m;
        float sc = bn1_g[tid] * rsqrtf(var + 1e-5f);
        sc1[tid] = sc;
        bi1[tid] = bn1_b[tid] - m * sc;
    }
    __syncthreads();
    int p = blockIdx.x * 256 + tid;
    if (p >= N_PIX) return;

    ull nv2[32];
    {
        const ull* np = (const ull*)&g_new[(size_t)p * 64];
#pragma unroll
        for (int i = 0; i < 32; i++) nv2[i] = np[i];
    }
    ull acc2[32];
#pragma unroll
    for (int i = 0; i < 32; i++) acc2[i] = 0ull;

#pragma unroll 2
    for (int dd = 0; dd < 64; dd++) {
        const float* wrow = &wot[dd * 64];
        ull xa2 = 0ull;
#pragma unroll
        for (int cp = 0; cp < 16; cp++) {
            ulonglong2 wv = *(const ulonglong2*)&wrow[cp * 4];
            fma2(xa2, wv.x, nv2[2 * cp]);
            fma2(xa2, wv.y, nv2[2 * cp + 1]);
        }
        float xa = fmaxf(hsum2(xa2) + bo_s[dd], 0.f);
        ull xd = fdup(xa);
        const float* arow = &w2a[dd * 64];
#pragma unroll
        for (int i = 0; i < 16; i++) {
            ulonglong2 wv = *(const ulonglong2*)&arow[i * 4];
            fma2(acc2[2 * i],     wv.x, xd);
            fma2(acc2[2 * i + 1], wv.y, xd);
        }
    }
    // h concat half, BN1+relu inline
#pragma unroll 1
    for (int c4 = 0; c4 < 64; c4 += 4) {
        float4 hv = *(const float4*)&g_h[(size_t)p * 64 + c4];
        float4 s4 = *(const float4*)&sc1[c4];
        float4 b4 = *(const float4*)&bi1[c4];
        float hval[4];
        hval[0] = fmaxf(fmaf(hv.x, s4.x, b4.x), 0.f);
        hval[1] = fmaxf(fmaf(hv.y, s4.y, b4.y), 0.f);
        hval[2] = fmaxf(fmaf(hv.z, s4.z, b4.z), 0.f);
        hval[3] = fmaxf(fmaf(hv.w, s4.w, b4.w), 0.f);
#pragma unroll
        for (int u = 0; u < 4; u++) {
            ull hd = fdup(hval[u]);
            const float* brow = &w2b[(c4 + u) * 64];
#pragma unroll
            for (int i = 0; i < 16; i++) {
                ulonglong2 wv = *(const ulonglong2*)&brow[i * 4];
                fma2(acc2[2 * i],     wv.x, hd);
                fma2(acc2[2 * i + 1], wv.y, hd);
            }
        }
    }
#pragma unroll
    for (int i = 0; i < 32; i++) {
        float2 f = u2f(acc2[i]);
        g_outpre[(size_t)(2 * i) * N_PIX + p]     = f.x;
        g_outpre[(size_t)(2 * i + 1) * N_PIX + p] = f.y;
    }
}

// ---------------- BN2 ----------------
__global__ void k_stats2(const float* __restrict__ g, const float* __restrict__ b) {
    __shared__ float sh[256], sh2[256];
    int c = blockIdx.x;
    const float* base = g_outpre + (size_t)c * N_PIX;
    float s = 0.f, s2 = 0.f;
    for (int p = threadIdx.x; p < N_PIX; p += 256) {
        float v = base[p];
        s += v; s2 += v * v;
    }
    sh[threadIdx.x] = s; sh2[threadIdx.x] = s2;
    __syncthreads();
    for (int off = 128; off > 0; off >>= 1) {
        if (threadIdx.x < off) {
            sh[threadIdx.x]  += sh[threadIdx.x + off];
            sh2[threadIdx.x] += sh2[threadIdx.x + off];
        }
        __syncthreads();
    }
    if (threadIdx.x == 0) {
        float m = sh[0] / (float)N_PIX;
        float var = sh2[0] / (float)N_PIX - m * m;
        float sc = g[c] * rsqrtf(var + 1e-5f);
        g_scale2[c] = sc;
        g_bias2[c]  = b[c] - m * sc;
    }
}

__global__ void k_apply2(float* __restrict__ out) {
    int i = blockIdx.x * 256 + threadIdx.x;
    if (i >= E_CH * N_PIX) return;
    int c = i / N_PIX;
    float v = g_outpre[i] * g_scale2[c] + g_bias2[c];
    out[i] = v > 0.f ? v : 0.f;
}

// ---------------- launch ----------------
extern "C" void kernel_launch(void* const* d_in, const int* in_sizes, int n_in,
                              void* d_out, int out_size) {
    const float* x         = (const float*)d_in[0];
    const int*   prop      = (const int*)d_in[1];
    const int*   rand_inds = (const int*)d_in[2];
    const float* w_conv1   = (const float*)d_in[3];
    const float* bn1_g     = (const float*)d_in[4];
    const float* bn1_b     = (const float*)d_in[5];
    const float* wq        = (const float*)d_in[6];
    const float* wkv       = (const float*)d_in[7];
    const float* w_out     = (const float*)d_in[8];
    const float* b_out     = (const float*)d_in[9];
    const float* w_conv2   = (const float*)d_in[10];
    const float* bn2_g     = (const float*)d_in[11];
    const float* bn2_b     = (const float*)d_in[12];
    float* out = (float*)d_out;

    size_t smem_c1 = (size_t)E_CH * C_IN * sizeof(float); // 64 KB
    cudaFuncSetAttribute(k_conv1, cudaFuncAttributeMaxDynamicSharedMemorySize, (int)smem_c1);
    cudaFuncSetAttribute(k_attn,  cudaFuncAttributeMaxDynamicSharedMemorySize, SM_ATT_BYTES);
    cudaFuncSetAttribute(k_fuse,  cudaFuncAttributeMaxDynamicSharedMemorySize, SM_FUSE_BYTES);

    k_init<<<1, 128>>>();
    k_scanA<<<SCAN_B, 256>>>(prop);
    k_scanB<<<1, 512>>>();
    k_scanC<<<SCAN_B, 256>>>(prop);
    k_conv1<<<(N_PIX + 255) / 256, 256, smem_c1>>>(x, w_conv1);
    k_attn<<<HEADS * CROP, ATT_THREADS, SM_ATT_BYTES>>>(wq, wkv, rand_inds, bn1_g, bn1_b);
    k_fuse<<<(N_PIX + 255) / 256, 256, SM_FUSE_BYTES>>>(w_out, b_out, w_conv2, bn1_g, bn1_b);
    k_stats2<<<E_CH, 256>>>(bn2_g, bn2_b);
    k_apply2<<<(E_CH * N_PIX + 255) / 256, 256>>>(out);
}

// round 4
// speedup vs baseline: 1.1315x; 1.0486x over previous
#include <cuda_runtime.h>
#include <math.h>

#define N_PIX    90000
#define HALF_PIX 45000
#define C_IN     256
#define E_CH     64
#define CROP     300
#define HEADS    2
#define DH       32

typedef unsigned long long ull;

__device__ __forceinline__ void fma2(ull& d, ull a, ull b) {
    asm("fma.rn.f32x2 %0, %1, %2, %0;" : "+l"(d) : "l"(a), "l"(b));
}
__device__ __forceinline__ ull add2(ull a, ull b) {
    ull r; asm("add.rn.f32x2 %0, %1, %2;" : "=l"(r) : "l"(a), "l"(b)); return r;
}
__device__ __forceinline__ ull mul2(ull a, ull b) {
    ull r; asm("mul.rn.f32x2 %0, %1, %2;" : "=l"(r) : "l"(a), "l"(b)); return r;
}
__device__ __forceinline__ ull fdup(float v) {
    ull r; asm("mov.b64 %0, {%1, %1};" : "=l"(r) : "f"(v)); return r;
}
__device__ __forceinline__ float2 u2f(ull v) {
    float2 f; asm("mov.b64 {%0, %1}, %2;" : "=f"(f.x), "=f"(f.y) : "l"(v)); return f;
}
__device__ __forceinline__ float hsum2(ull v) { float2 f = u2f(v); return f.x + f.y; }

// ---------------- scratch ----------------
__device__ float g_h[N_PIX * E_CH];        // [p][c] pre-BN1
__device__ float g_new[N_PIX * E_CH];      // [p][c] attention scatter target
__device__ float g_outpre[E_CH * N_PIX];   // [c][p] pre-BN2
__device__ int   g_obj[HALF_PIX];
__device__ int   g_bg[HALF_PIX];
__device__ int   g_blkcnt[360];
__device__ float g_sum1[E_CH], g_sumsq1[E_CH];
__device__ float g_scale2[E_CH], g_bias2[E_CH];

// ---------------- scanA (also zeroes BN1 accumulators in block 0) ----------------
#define SCAN_B 352
__global__ void k_scanA(const int* __restrict__ prop) {
    if (blockIdx.x == 0 && threadIdx.x < 128) {
        if (threadIdx.x < 64) g_sum1[threadIdx.x] = 0.f;
        else g_sumsq1[threadIdx.x - 64] = 0.f;
    }
    int idx = blockIdx.x * 256 + threadIdx.x;
    int v = (idx < N_PIX) ? (prop[idx] != 0) : 0;
    unsigned m = __ballot_sync(0xffffffffu, v);
    __shared__ int wc[8];
    if ((threadIdx.x & 31) == 0) wc[threadIdx.x >> 5] = __popc(m);
    __syncthreads();
    if (threadIdx.x == 0) {
        int t = 0;
        for (int w = 0; w < 8; w++) t += wc[w];
        g_blkcnt[blockIdx.x] = t;
    }
}

// ---------------- scanBC: per-block prefix + scatter (merged) ----------------
__global__ void k_scanBC(const int* __restrict__ prop) {
    int tid = threadIdx.x;
    int b = blockIdx.x;
    // block-exclusive prefix of obj counts
    int acc = 0;
    for (int i = tid; i < b; i += 256) acc += g_blkcnt[i];
    __shared__ int red[256];
    red[tid] = acc;
    __syncthreads();
    for (int off = 128; off > 0; off >>= 1) {
        if (tid < off) red[tid] += red[tid + off];
        __syncthreads();
    }
    int blkobj = red[0];

    int idx = b * 256 + tid;
    int valid = idx < N_PIX;
    int v = valid ? (prop[idx] != 0) : 0;
    unsigned objm = __ballot_sync(0xffffffffu, v);
    unsigned valm = __ballot_sync(0xffffffffu, valid);
    int lane = tid & 31, w = tid >> 5;
    __shared__ int wobj[8], wval[8];
    if (lane == 0) { wobj[w] = __popc(objm); wval[w] = __popc(valm); }
    __syncthreads();
    int objbase = 0, valbase = 0;
    for (int i = 0; i < w; i++) { objbase += wobj[i]; valbase += wval[i]; }
    unsigned ltm = (1u << lane) - 1u;
    if (valid) {
        if (v) {
            g_obj[blkobj + objbase + __popc(objm & ltm)] = idx;
        } else {
            int bg_before_blk = b * 256 - blkobj;
            int intra = (valbase - objbase) + (__popc(valm & ltm) - __popc(objm & ltm));
            g_bg[bg_before_blk + intra] = idx;
        }
    }
}

// ---------------- conv1 with fused BN1 stats ----------------
__global__ __launch_bounds__(256) void k_conv1(const float* __restrict__ x,
                                               const float* __restrict__ w) {
    extern __shared__ float ws[]; // transposed [c][e]
    int tid = threadIdx.x;
    for (int i = tid; i < E_CH * C_IN; i += 256) {
        int e = i >> 8, c = i & 255;
        ws[c * 64 + e] = w[i];
    }
    __syncthreads();
    int p = blockIdx.x * 256 + tid;
    bool valid = p < N_PIX;

    ull acc2[32];
#pragma unroll
    for (int i = 0; i < 32; i++) acc2[i] = 0ull;

    if (valid) {
#pragma unroll 2
        for (int c = 0; c < C_IN; c++) {
            ull xd = fdup(__ldg(&x[(size_t)c * N_PIX + p]));
            const float* wr = &ws[c * 64];
#pragma unroll
            for (int i = 0; i < 16; i++) {
                ulonglong2 wv = *(const ulonglong2*)&wr[i * 4];
                fma2(acc2[2 * i],     wv.x, xd);
                fma2(acc2[2 * i + 1], wv.y, xd);
            }
        }
        ull* op = (ull*)&g_h[(size_t)p * 64];
#pragma unroll
        for (int i = 0; i < 32; i++) op[i] = acc2[i];
    }

    int lane = tid & 31;
#pragma unroll 4
    for (int k = 0; k < 32; k++) {
        ull s = acc2[k];
        ull q = mul2(acc2[k], acc2[k]);
#pragma unroll
        for (int o = 16; o > 0; o >>= 1) {
            s = add2(s, __shfl_xor_sync(0xffffffffu, s, o));
            q = add2(q, __shfl_xor_sync(0xffffffffu, q, o));
        }
        if (lane == 0) {
            float2 sf = u2f(s), qf = u2f(q);
            atomicAdd(&g_sum1[2 * k],     sf.x);
            atomicAdd(&g_sum1[2 * k + 1], sf.y);
            atomicAdd(&g_sumsq1[2 * k],     qf.x);
            atomicAdd(&g_sumsq1[2 * k + 1], qf.y);
        }
    }
}

// ---------------- attention ----------------
#define ATT_THREADS 384
#define ATT_WARPS 12
// floats: sc1 64 | bi1 64 | wq_t 1152 | wk_t 1152 | wv_t 1152 | p/seq 14400 | q 9600 | k 9600 | v 9600 | pix 300
#define SM_ATT_FLOATS (64 + 64 + 1152 * 3 + 14400 + 9600 * 3 + 300)
#define SM_ATT_BYTES (SM_ATT_FLOATS * 4)

__global__ __launch_bounds__(ATT_THREADS, 1) void k_attn(const float* __restrict__ wq,
                                                         const float* __restrict__ wkv,
                                                         const int* __restrict__ rand_inds,
                                                         const float* __restrict__ bn1_g,
                                                         const float* __restrict__ bn1_b) {
    extern __shared__ float sm[];
    float* sc1    = sm;                    // 64
    float* bi1    = sm + 64;               // 64
    float* wq_t   = sm + 128;              // 32*36
    float* wk_t   = wq_t + 1152;           // 32*36
    float* wv_t   = wk_t + 1152;           // 32*36
    float* p_rows = wv_t + 1152;           // 14400 (seq_s alias during gather/QKV)
    float* q_s    = p_rows + 14400;        // 9600
    float* k_s    = q_s + 9600;            // 9600
    float* v_t    = k_s + 9600;            // 9600 : [d][300]
    int*   pix_s  = (int*)(v_t + 9600);    // 300
    float* seq_s  = p_rows;

    int tid = threadIdx.x, warp = tid >> 5, lane = tid & 31;
    int b = blockIdx.x;
    int head = b / CROP;
    int iblk = b - head * CROP;
    int hoff = head * DH;

    if (tid < 64) {
        float m = g_sum1[tid] * (1.f / (float)N_PIX);
        float var = g_sumsq1[tid] * (1.f / (float)N_PIX) - m * m;
        float sc = bn1_g[tid] * rsqrtf(var + 1e-5f);
        sc1[tid] = sc;
        bi1[tid] = bn1_b[tid] - m * sc;
    }
    const int* src = (iblk < CROP / 2) ? g_obj : g_bg;
    const int* ri = rand_inds + (size_t)head * N_PIX + (size_t)iblk * CROP;
    for (int j = tid; j < CROP; j += ATT_THREADS) pix_s[j] = src[ri[j]];
    // weights transposed: stride 36 rows (conflict-free LDS128 over lanes)
    for (int i = tid; i < 1024; i += ATT_THREADS) {
        int e = i >> 5, d = i & 31;
        wq_t[d * 36 + e] = wq[i];
    }
    for (int i = tid; i < 2048; i += ATT_THREADS) {
        int e = i >> 6, c = i & 63;
        if (c < 32) wk_t[c * 36 + e] = wkv[i];
        else        wv_t[(c - 32) * 36 + e] = wkv[i];
    }
    __syncthreads();

    // gather + BN1 + relu, XOR-swizzled [j][32]
    for (int u = tid; u < CROP * 8; u += ATT_THREADS) {
        int j = u >> 3, seg = u & 7;
        int ch = hoff + seg * 4;
        float4 v = *(const float4*)&g_h[(size_t)pix_s[j] * 64 + ch];
        float4 s4 = *(const float4*)&sc1[ch];
        float4 b4 = *(const float4*)&bi1[ch];
        v.x = fmaxf(fmaf(v.x, s4.x, b4.x), 0.f);
        v.y = fmaxf(fmaf(v.y, s4.y, b4.y), 0.f);
        v.z = fmaxf(fmaf(v.z, s4.z, b4.z), 0.f);
        v.w = fmaxf(fmaf(v.w, s4.w, b4.w), 0.f);
        int pc = seg ^ (j & 7);
        *(float4*)&seq_s[j * 32 + pc * 4] = v;
    }
    __syncthreads();

    // QKV: packed f32x2 over e; q/k swizzled [j][32]; v transposed [d][300]
    {
        int d = lane;
        for (int j = warp; j < CROP; j += ATT_WARPS) {
            int sw2 = (j & 7) << 2;
            ull aq = 0, ak = 0, av = 0;
#pragma unroll
            for (int e4 = 0; e4 < 8; e4++) {
                ulonglong2 sp = *(const ulonglong2*)&seq_s[j * 32 + ((e4 << 2) ^ sw2)];
                ulonglong2 wqv = *(const ulonglong2*)&wq_t[d * 36 + (e4 << 2)];
                ulonglong2 wkk = *(const ulonglong2*)&wk_t[d * 36 + (e4 << 2)];
                ulonglong2 wvv = *(const ulonglong2*)&wv_t[d * 36 + (e4 << 2)];
                fma2(aq, sp.x, wqv.x);
                fma2(ak, sp.x, wkk.x);
                fma2(av, sp.x, wvv.x);
                fma2(aq, sp.y, wqv.y);
                fma2(ak, sp.y, wkk.y);
                fma2(av, sp.y, wvv.y);
            }
            int wi = j * 32 + (d ^ sw2);
            q_s[wi] = hsum2(aq);
            k_s[wi] = hsum2(ak);
            v_t[d * 300 + j] = hsum2(av);
        }
    }
    __syncthreads();

    const float scale = 0.17677669529663687f; // 1/sqrt(32)
    float* pw = &p_rows[warp * 4 * 300];
    for (int rp = warp; rp < 75; rp += ATT_WARPS) {
        int r0 = rp * 4;
        ull a[4][10];
#pragma unroll
        for (int r = 0; r < 4; r++)
#pragma unroll
            for (int jj = 0; jj < 10; jj++) a[r][jj] = 0ull;

#pragma unroll
        for (int c = 0; c < 8; c++) {
            ull qx[4], qy[4];
#pragma unroll
            for (int r = 0; r < 4; r++) {
                int row = r0 + r;
                ulonglong2 t = *(const ulonglong2*)&q_s[row * 32 + ((c << 2) ^ ((row & 7) << 2))];
                qx[r] = t.x; qy[r] = t.y;
            }
#pragma unroll
            for (int jj = 0; jj < 10; jj++) {
                int j = lane + (jj << 5);
                int jc = (j < CROP) ? j : 0;
                ulonglong2 kv = *(const ulonglong2*)&k_s[jc * 32 + ((c << 2) ^ ((jc & 7) << 2))];
                fma2(a[0][jj], qx[0], kv.x);
                fma2(a[1][jj], qx[1], kv.x);
                fma2(a[2][jj], qx[2], kv.x);
                fma2(a[3][jj], qx[3], kv.x);
                fma2(a[0][jj], qy[0], kv.y);
                fma2(a[1][jj], qy[1], kv.y);
                fma2(a[2][jj], qy[2], kv.y);
                fma2(a[3][jj], qy[3], kv.y);
            }
        }
        // softmax per row (registers -> p_rows normalized)
#pragma unroll
        for (int r = 0; r < 4; r++) {
            float sv[10];
            float mx = -1e30f;
#pragma unroll
            for (int jj = 0; jj < 10; jj++) {
                float s = hsum2(a[r][jj]) * scale;
                sv[jj] = s;
                if (lane + (jj << 5) < CROP) mx = fmaxf(mx, s);
            }
#pragma unroll
            for (int o = 16; o > 0; o >>= 1)
                mx = fmaxf(mx, __shfl_xor_sync(0xffffffffu, mx, o));
            float sum = 0.f;
#pragma unroll
            for (int jj = 0; jj < 10; jj++) {
                int j = lane + (jj << 5);
                float e = (j < CROP) ? __expf(sv[jj] - mx) : 0.f;
                sv[jj] = e;
                sum += e;
            }
#pragma unroll
            for (int o = 16; o > 0; o >>= 1)
                sum += __shfl_xor_sync(0xffffffffu, sum, o);
            float inv = 1.f / sum;
#pragma unroll
            for (int jj = 0; jj < 10; jj++) {
                int j = lane + (jj << 5);
                if (j < CROP) pw[r * 300 + j] = sv[jj] * inv;
            }
        }
        __syncwarp();
        // PV: lane=d; 8 accumulators
        ull oa[4] = {0, 0, 0, 0}, ob[4] = {0, 0, 0, 0};
        const float* vrow = &v_t[lane * 300];
#pragma unroll 5
        for (int j4 = 0; j4 < 75; j4++) {
            ulonglong2 vv = *(const ulonglong2*)&vrow[j4 * 4];
#pragma unroll
            for (int r = 0; r < 4; r++) {
                ulonglong2 pv = *(const ulonglong2*)&pw[r * 300 + j4 * 4];
                fma2(oa[r], pv.x, vv.x);
                fma2(ob[r], pv.y, vv.y);
            }
        }
#pragma unroll
        for (int r = 0; r < 4; r++) {
            float ov = hsum2(add2(oa[r], ob[r]));
            int t = (r0 + r) * 32 + lane;
            int d = t / 300, mm = t - d * 300;
            g_new[(size_t)pix_s[mm] * 64 + hoff + d] = ov;
        }
        __syncwarp();
    }
}

// ---------------- fused w_out(+relu) + conv2 ----------------
#define SM_FUSE_BYTES ((3 * 4096 + 64 + 128) * 4)
__global__ __launch_bounds__(256) void k_fuse(const float* __restrict__ w_out,
                                              const float* __restrict__ b_out,
                                              const float* __restrict__ w2,
                                              const float* __restrict__ bn1_g,
                                              const float* __restrict__ bn1_b) {
    extern __shared__ float sf[];
    float* wot  = sf;              // [d][c]
    float* w2a  = wot + 4096;      // [d][o]
    float* w2b  = w2a + 4096;      // [c][o]
    float* bo_s = w2b + 4096;      // 64
    float* sc1  = bo_s + 64;
    float* bi1  = sc1 + 64;
    int tid = threadIdx.x;
    for (int i = tid; i < 4096; i += 256) {
        int r = i >> 6, c = i & 63;
        wot[c * 64 + r] = w_out[i];
        w2a[c * 64 + r] = w2[r * 128 + c];
        w2b[c * 64 + r] = w2[r * 128 + 64 + c];
    }
    if (tid < 64) {
        bo_s[tid] = b_out[tid];
        float m = g_sum1[tid] * (1.f / (float)N_PIX);
        float var = g_sumsq1[tid] * (1.f / (float)N_PIX) - m * m;
        float sc = bn1_g[tid] * rsqrtf(var + 1e-5f);
        sc1[tid] = sc;
        bi1[tid] = bn1_b[tid] - m * sc;
    }
    __syncthreads();
    int p = blockIdx.x * 256 + tid;
    if (p >= N_PIX) return;

    ull nv2[32];
    {
        const ull* np = (const ull*)&g_new[(size_t)p * 64];
#pragma unroll
        for (int i = 0; i < 32; i++) nv2[i] = np[i];
    }
    ull acc2[32];
#pragma unroll
    for (int i = 0; i < 32; i++) acc2[i] = 0ull;

#pragma unroll 2
    for (int dd = 0; dd < 64; dd++) {
        const float* wrow = &wot[dd * 64];
        ull xs0 = 0, xs1 = 0, xs2 = 0, xs3 = 0;
#pragma unroll
        for (int cp = 0; cp < 16; cp += 2) {
            ulonglong2 wv0 = *(const ulonglong2*)&wrow[cp * 4];
            ulonglong2 wv1 = *(const ulonglong2*)&wrow[cp * 4 + 4];
            fma2(xs0, wv0.x, nv2[2 * cp]);
            fma2(xs1, wv0.y, nv2[2 * cp + 1]);
            fma2(xs2, wv1.x, nv2[2 * cp + 2]);
            fma2(xs3, wv1.y, nv2[2 * cp + 3]);
        }
        float xa = fmaxf(hsum2(add2(add2(xs0, xs1), add2(xs2, xs3))) + bo_s[dd], 0.f);
        ull xd = fdup(xa);
        const float* arow = &w2a[dd * 64];
#pragma unroll
        for (int i = 0; i < 16; i++) {
            ulonglong2 wv = *(const ulonglong2*)&arow[i * 4];
            fma2(acc2[2 * i],     wv.x, xd);
            fma2(acc2[2 * i + 1], wv.y, xd);
        }
    }
#pragma unroll 1
    for (int c4 = 0; c4 < 64; c4 += 4) {
        float4 hv = *(const float4*)&g_h[(size_t)p * 64 + c4];
        float4 s4 = *(const float4*)&sc1[c4];
        float4 b4 = *(const float4*)&bi1[c4];
        float hval[4];
        hval[0] = fmaxf(fmaf(hv.x, s4.x, b4.x), 0.f);
        hval[1] = fmaxf(fmaf(hv.y, s4.y, b4.y), 0.f);
        hval[2] = fmaxf(fmaf(hv.z, s4.z, b4.z), 0.f);
        hval[3] = fmaxf(fmaf(hv.w, s4.w, b4.w), 0.f);
#pragma unroll
        for (int u = 0; u < 4; u++) {
            ull hd = fdup(hval[u]);
            const float* brow = &w2b[(c4 + u) * 64];
#pragma unroll
            for (int i = 0; i < 16; i++) {
                ulonglong2 wv = *(const ulonglong2*)&brow[i * 4];
                fma2(acc2[2 * i],     wv.x, hd);
                fma2(acc2[2 * i + 1], wv.y, hd);
            }
        }
    }
#pragma unroll
    for (int i = 0; i < 32; i++) {
        float2 f = u2f(acc2[i]);
        g_outpre[(size_t)(2 * i) * N_PIX + p]     = f.x;
        g_outpre[(size_t)(2 * i + 1) * N_PIX + p] = f.y;
    }
}

// ---------------- BN2 ----------------
__global__ void k_stats2(const float* __restrict__ g, const float* __restrict__ b) {
    __shared__ float sh[256], sh2[256];
    int c = blockIdx.x;
    const float* base = g_outpre + (size_t)c * N_PIX;
    float s = 0.f, s2 = 0.f;
    for (int p = threadIdx.x; p < N_PIX; p += 256) {
        float v = base[p];
        s += v; s2 += v * v;
    }
    sh[threadIdx.x] = s; sh2[threadIdx.x] = s2;
    __syncthreads();
    for (int off = 128; off > 0; off >>= 1) {
        if (threadIdx.x < off) {
            sh[threadIdx.x]  += sh[threadIdx.x + off];
            sh2[threadIdx.x] += sh2[threadIdx.x + off];
        }
        __syncthreads();
    }
    if (threadIdx.x == 0) {
        float m = sh[0] / (float)N_PIX;
        float var = sh2[0] / (float)N_PIX - m * m;
        float sc = g[c] * rsqrtf(var + 1e-5f);
        g_scale2[c] = sc;
        g_bias2[c]  = b[c] - m * sc;
    }
}

__global__ void k_apply2(float* __restrict__ out) {
    int i = blockIdx.x * 256 + threadIdx.x;
    if (i >= E_CH * N_PIX) return;
    int c = i / N_PIX;
    float v = g_outpre[i] * g_scale2[c] + g_bias2[c];
    out[i] = v > 0.f ? v : 0.f;
}

// ---------------- launch ----------------
extern "C" void kernel_launch(void* const* d_in, const int* in_sizes, int n_in,
                              void* d_out, int out_size) {
    const float* x         = (const float*)d_in[0];
    const int*   prop      = (const int*)d_in[1];
    const int*   rand_inds = (const int*)d_in[2];
    const float* w_conv1   = (const float*)d_in[3];
    const float* bn1_g     = (const float*)d_in[4];
    const float* bn1_b     = (const float*)d_in[5];
    const float* wq        = (const float*)d_in[6];
    const float* wkv       = (const float*)d_in[7];
    const float* w_out     = (const float*)d_in[8];
    const float* b_out     = (const float*)d_in[9];
    const float* w_conv2   = (const float*)d_in[10];
    const float* bn2_g     = (const float*)d_in[11];
    const float* bn2_b     = (const float*)d_in[12];
    float* out = (float*)d_out;

    size_t smem_c1 = (size_t)E_CH * C_IN * sizeof(float);
    cudaFuncSetAttribute(k_conv1, cudaFuncAttributeMaxDynamicSharedMemorySize, (int)smem_c1);
    cudaFuncSetAttribute(k_attn,  cudaFuncAttributeMaxDynamicSharedMemorySize, SM_ATT_BYTES);
    cudaFuncSetAttribute(k_fuse,  cudaFuncAttributeMaxDynamicSharedMemorySize, SM_FUSE_BYTES);

    k_scanA<<<SCAN_B, 256>>>(prop);
    k_scanBC<<<SCAN_B, 256>>>(prop);
    k_conv1<<<(N_PIX + 255) / 256, 256, smem_c1>>>(x, w_conv1);
    k_attn<<<HEADS * CROP, ATT_THREADS, SM_ATT_BYTES>>>(wq, wkv, rand_inds, bn1_g, bn1_b);
    k_fuse<<<(N_PIX + 255) / 256, 256, SM_FUSE_BYTES>>>(w_out, b_out, w_conv2, bn1_g, bn1_b);
    k_stats2<<<E_CH, 256>>>(bn2_g, bn2_b);
    k_apply2<<<(E_CH * N_PIX + 255) / 256, 256>>>(out);
}